// round 9
// baseline (speedup 1.0000x reference)
#include <cuda_runtime.h>
#include <math.h>
#include <stdint.h>

// ---------------- problem constants ----------------
#define BB   512
#define NN   196          // 14*14
#define NQ   49           // 7*7
#define CC   256
#define HH   8
#define KD   16
#define VD   32
#define KV_DIM 384        // H*(KD+VD)
#define Q_DIM  128        // H*KD
#define V_ATTN 256        // H*VD
#define OUT_DIM 384
#define EPS  1e-5f
#define ATT_SCALE 0.25f   // 16^-0.5

// ---------------- scratch (module-static, allowed) ----------------
__device__ float g_kv_buf[(size_t)BB * NN * KV_DIM];   // 154 MB
__device__ float g_q_buf [(size_t)BB * NQ * Q_DIM];    // 12.8 MB
__device__ float g_o_buf [(size_t)BB * NQ * V_ATTN];   // 25.7 MB
__device__ float g_bias_buf[HH * NQ * NN];             // 307 KB

__device__ __forceinline__ float hswish(float x) {
    float c = fminf(fmaxf(x + 3.0f, 0.0f), 6.0f);
    return x * c * (1.0f / 6.0f);
}

__device__ __forceinline__ uint32_t f2tf(float x) {
    uint32_t r;
    asm("cvt.rna.tf32.f32 %0, %1;" : "=r"(r) : "f"(x));
    return r;
}

__device__ __forceinline__ void mma_tf32(float* c, const uint32_t* a,
                                         uint32_t b0, uint32_t b1) {
    asm volatile(
        "mma.sync.aligned.m16n8k8.row.col.f32.tf32.tf32.f32 "
        "{%0,%1,%2,%3}, {%4,%5,%6,%7}, {%8,%9}, {%0,%1,%2,%3};\n"
        : "+f"(c[0]), "+f"(c[1]), "+f"(c[2]), "+f"(c[3])
        : "r"(a[0]), "r"(a[1]), "r"(a[2]), "r"(a[3]), "r"(b0), "r"(b1));
}

// ---------------------------------------------------------------------------
// TF32 tensor-core GEMM + norm epilogue.
// MODE 0: A' = A;  MODE 1: subsample gather;  MODE 2: hardswish(A).
// ---------------------------------------------------------------------------
template <int MODE>
__global__ __launch_bounds__(256)
void gemm_tf32(const float* __restrict__ A, const float* __restrict__ W,
               const float* __restrict__ gv, const float* __restrict__ bv,
               const float* __restrict__ mv, const float* __restrict__ vv,
               float* __restrict__ out, int Ncols)
{
    __shared__ uint32_t As[2][128][20];
    __shared__ uint32_t Bs[2][128][20];

    const int t    = threadIdx.x;
    const int lane = t & 31;
    const int warp = t >> 5;
    const int wm   = warp >> 1;
    const int wn   = warp & 1;
    const int m0   = blockIdx.y * 128;
    const int n0   = blockIdx.x * 128;

    const int lrow = t >> 2;
    const int lk4  = (t & 3) * 4;

    const float* Aptr[2];
#pragma unroll
    for (int r = 0; r < 2; r++) {
        int gm = m0 + lrow + r * 64;
        if (MODE == 1) {
            int b  = gm / NQ;
            int qq = gm - b * NQ;
            int n  = 28 * (qq / 7) + 2 * (qq % 7);
            Aptr[r] = A + ((size_t)(b * NN + n)) * CC;
        } else {
            Aptr[r] = A + (size_t)gm * CC;
        }
    }
    const float* Bptr[2];
#pragma unroll
    for (int r = 0; r < 2; r++)
        Bptr[r] = W + (size_t)(n0 + lrow + r * 64) * CC;

    float acc[2][8][4];
#pragma unroll
    for (int i = 0; i < 2; i++)
#pragma unroll
        for (int j = 0; j < 8; j++)
#pragma unroll
            for (int k = 0; k < 4; k++) acc[i][j][k] = 0.0f;

    float4 av[2], bv4[2];
#pragma unroll
    for (int r = 0; r < 2; r++) {
        av[r]  = *(const float4*)(Aptr[r] + lk4);
        bv4[r] = *(const float4*)(Bptr[r] + lk4);
    }

    int buf = 0;
    const int lq = lane >> 2;
    const int lr4 = lane & 3;

    for (int c = 0; c < CC / 16; c++) {
#pragma unroll
        for (int r = 0; r < 2; r++) {
            int row = lrow + r * 64;
            float4 a = av[r];
            if (MODE == 2) {
                a.x = hswish(a.x); a.y = hswish(a.y);
                a.z = hswish(a.z); a.w = hswish(a.w);
            }
            As[buf][row][lk4 + 0] = f2tf(a.x);
            As[buf][row][lk4 + 1] = f2tf(a.y);
            As[buf][row][lk4 + 2] = f2tf(a.z);
            As[buf][row][lk4 + 3] = f2tf(a.w);
            Bs[buf][row][lk4 + 0] = f2tf(bv4[r].x);
            Bs[buf][row][lk4 + 1] = f2tf(bv4[r].y);
            Bs[buf][row][lk4 + 2] = f2tf(bv4[r].z);
            Bs[buf][row][lk4 + 3] = f2tf(bv4[r].w);
        }
        __syncthreads();

        if (c + 1 < CC / 16) {
            int k0 = (c + 1) * 16;
#pragma unroll
            for (int r = 0; r < 2; r++) {
                av[r]  = *(const float4*)(Aptr[r] + k0 + lk4);
                bv4[r] = *(const float4*)(Bptr[r] + k0 + lk4);
            }
        }

#pragma unroll
        for (int ks = 0; ks < 16; ks += 8) {
            uint32_t a[2][4];
#pragma unroll
            for (int mt = 0; mt < 2; mt++) {
                int mb = wm * 32 + mt * 16;
                a[mt][0] = As[buf][mb + lq    ][ks + lr4];
                a[mt][1] = As[buf][mb + lq + 8][ks + lr4];
                a[mt][2] = As[buf][mb + lq    ][ks + lr4 + 4];
                a[mt][3] = As[buf][mb + lq + 8][ks + lr4 + 4];
            }
#pragma unroll
            for (int nt = 0; nt < 8; nt++) {
                int nb = wn * 64 + nt * 8;
                uint32_t b0 = Bs[buf][nb + lq][ks + lr4];
                uint32_t b1 = Bs[buf][nb + lq][ks + lr4 + 4];
                mma_tf32(acc[0][nt], a[0], b0, b1);
                mma_tf32(acc[1][nt], a[1], b0, b1);
            }
        }
        buf ^= 1;
    }

#pragma unroll
    for (int mt = 0; mt < 2; mt++) {
        int mrow = m0 + wm * 32 + mt * 16 + lq;
#pragma unroll
        for (int nt = 0; nt < 8; nt++) {
            int n = n0 + wn * 64 + nt * 8 + lr4 * 2;
            float s0 = gv[n]     * rsqrtf(vv[n]     + EPS);
            float s1 = gv[n + 1] * rsqrtf(vv[n + 1] + EPS);
            float m_0 = mv[n], m_1 = mv[n + 1];
            float o_0 = bv[n], o_1 = bv[n + 1];
            const float* cc = acc[mt][nt];
            float2 r0 = { (cc[0] - m_0) * s0 + o_0, (cc[1] - m_1) * s1 + o_1 };
            float2 r1 = { (cc[2] - m_0) * s0 + o_0, (cc[3] - m_1) * s1 + o_1 };
            *(float2*)(out + (size_t)mrow * Ncols + n)       = r0;
            *(float2*)(out + (size_t)(mrow + 8) * Ncols + n) = r1;
        }
    }
}

// ---------------------------------------------------------------------------
// Bias gather precompute: g_bias_buf[h][q][k] = biases[h, bias_idxs[q,k]]
// ---------------------------------------------------------------------------
__global__ void bias_gather(const float* __restrict__ biases,
                            const int* __restrict__ bidx)
{
    const int q = blockIdx.x;
    const int h = blockIdx.y;
    for (int k = threadIdx.x; k < NN; k += blockDim.x)
        g_bias_buf[(h * NQ + q) * NN + k] = biases[h * NN + bidx[q * NN + k]];
}

// ---------------------------------------------------------------------------
// Attention, register-cached: 7 warps per (b,h); each warp owns 7 queries.
// Lane owns key k = 32*s + lane per s-group; K row cached in regs, q and p
// distributed via shuffle. smem traffic per block ~0.27MB (was ~1.9MB).
// ---------------------------------------------------------------------------
#define ATT_THREADS 224
__global__ __launch_bounds__(ATT_THREADS)
void attn_kernel()
{
    __shared__ float ks[NN * 20];      // K rows padded to 20 floats (LDS.128 cf)
    __shared__ float vs[NN * VD];      // [k][vd]
    __shared__ float qs[NQ * KD];

    const int bh = blockIdx.x;
    const int b = bh >> 3, h = bh & 7;
    const int t = threadIdx.x;

    const float* kvbase = g_kv_buf + (size_t)b * NN * KV_DIM + h * (KD + VD);
    for (int idx = t; idx < NN * KD; idx += ATT_THREADS) {
        int n = idx >> 4, d = idx & 15;
        ks[n * 20 + d] = kvbase[n * KV_DIM + d];
    }
    for (int idx = t; idx < NN * VD; idx += ATT_THREADS) {
        int n = idx >> 5, d = idx & 31;
        vs[idx] = kvbase[n * KV_DIM + KD + d];
    }
    const float* qbase = g_q_buf + (size_t)b * NQ * Q_DIM + h * KD;
    for (int idx = t; idx < NQ * KD; idx += ATT_THREADS) {
        int n = idx >> 4, d = idx & 15;
        qs[idx] = qbase[n * Q_DIM + d];
    }
    __syncthreads();

    const int w    = t >> 5;
    const int lane = t & 31;
    const int q0   = w * 7;            // warp's 7 queries: q0..q0+6

    // lane d (d = lane&15) holds q[q0+qi][d]; lanes 16-31 mirror
    float qv[7];
#pragma unroll
    for (int qi = 0; qi < 7; qi++)
        qv[qi] = qs[(q0 + qi) * KD + (lane & 15)];

    // ---- logits: lane's key for group s is k = 32s + lane ----
    float lg[7][7];                    // [qi][s]
#pragma unroll
    for (int s = 0; s < 7; s++) {
        const int k = 32 * s + lane;
        const bool valid = (k < NN);
        const int ksafe = valid ? k : 0;

        float kr[16];
        {
            const float4* kp = (const float4*)(ks + ksafe * 20);
            float4 v0 = kp[0], v1 = kp[1], v2 = kp[2], v3 = kp[3];
            kr[0]=v0.x; kr[1]=v0.y; kr[2]=v0.z; kr[3]=v0.w;
            kr[4]=v1.x; kr[5]=v1.y; kr[6]=v1.z; kr[7]=v1.w;
            kr[8]=v2.x; kr[9]=v2.y; kr[10]=v2.z; kr[11]=v2.w;
            kr[12]=v3.x; kr[13]=v3.y; kr[14]=v3.z; kr[15]=v3.w;
        }
        const float* bgb = g_bias_buf + (h * NQ + q0) * NN + ksafe;
#pragma unroll
        for (int qi = 0; qi < 7; qi++) {
            float d0 = 0.0f;
#pragma unroll
            for (int d = 0; d < KD; d++)
                d0 += __shfl_sync(0xffffffffu, qv[qi], d) * kr[d];
            lg[qi][s] = valid ? d0 * ATT_SCALE + __ldg(bgb + qi * NN)
                              : -1e30f;
        }
    }

    // ---- softmax per query (registers + warp reductions) ----
#pragma unroll
    for (int qi = 0; qi < 7; qi++) {
        float mx = lg[qi][0];
#pragma unroll
        for (int s = 1; s < 7; s++) mx = fmaxf(mx, lg[qi][s]);
#pragma unroll
        for (int o = 16; o > 0; o >>= 1)
            mx = fmaxf(mx, __shfl_xor_sync(0xffffffffu, mx, o));
        float sum = 0.0f;
#pragma unroll
        for (int s = 0; s < 7; s++) {
            float p = __expf(lg[qi][s] - mx);
            lg[qi][s] = p;
            sum += p;
        }
#pragma unroll
        for (int o = 16; o > 0; o >>= 1)
            sum += __shfl_xor_sync(0xffffffffu, sum, o);
        float inv = 1.0f / sum;
#pragma unroll
        for (int s = 0; s < 7; s++) lg[qi][s] *= inv;
    }

    // ---- AV: lane = vd; p fetched by shuffle from key-owner lane ----
    float ov[7];
#pragma unroll
    for (int qi = 0; qi < 7; qi++) ov[qi] = 0.0f;

#pragma unroll
    for (int s = 0; s < 7; s++) {
        const int kmax = (s == 6) ? (NN - 192) : 32;   // 4 for last group
        const float* vrow = vs + 32 * s * VD + lane;
        for (int src = 0; src < kmax; src++) {
            float v = vrow[src * VD];
#pragma unroll
            for (int qi = 0; qi < 7; qi++)
                ov[qi] += __shfl_sync(0xffffffffu, lg[qi][s], src) * v;
        }
    }

    float* obase = g_o_buf + ((size_t)(b * NQ + q0)) * V_ATTN + h * VD + lane;
#pragma unroll
    for (int qi = 0; qi < 7; qi++)
        obase[qi * V_ATTN] = ov[qi];
}

// ---------------------------------------------------------------------------
extern "C" void kernel_launch(void* const* d_in, const int* in_sizes, int n_in,
                              void* d_out, int out_size)
{
    const float* x      = (const float*)d_in[0];
    const float* W_kv   = (const float*)d_in[1];
    const float* gkv    = (const float*)d_in[2];
    const float* bkv    = (const float*)d_in[3];
    const float* mkv    = (const float*)d_in[4];
    const float* vkv    = (const float*)d_in[5];
    const float* W_q    = (const float*)d_in[6];
    const float* gq     = (const float*)d_in[7];
    const float* bq     = (const float*)d_in[8];
    const float* mq     = (const float*)d_in[9];
    const float* vq     = (const float*)d_in[10];
    const float* W_proj = (const float*)d_in[11];
    const float* gp     = (const float*)d_in[12];
    const float* bp     = (const float*)d_in[13];
    const float* mp     = (const float*)d_in[14];
    const float* vp     = (const float*)d_in[15];
    const float* biases = (const float*)d_in[16];
    const int*   bidx   = (const int*)  d_in[17];

    float *kvp, *qp, *op;
    cudaGetSymbolAddress((void**)&kvp, g_kv_buf);
    cudaGetSymbolAddress((void**)&qp,  g_q_buf);
    cudaGetSymbolAddress((void**)&op,  g_o_buf);

    // K0: bias gather table (tiny)
    bias_gather<<<dim3(NQ, HH), 196>>>(biases, bidx);

    // K1: kv = linear_norm(x, W_kv)  -- tf32 MMA
    gemm_tf32<0><<<dim3(KV_DIM / 128, (BB * NN) / 128), 256>>>(
        x, W_kv, gkv, bkv, mkv, vkv, kvp, KV_DIM);

    // K2: q = linear_norm(subsample(x), W_q) -- tf32 MMA
    gemm_tf32<1><<<dim3(Q_DIM / 128, (BB * NQ) / 128), 256>>>(
        x, W_q, gq, bq, mq, vq, qp, Q_DIM);

    // K3: attention per (b, h) -- register-cached
    attn_kernel<<<BB * HH, ATT_THREADS>>>();

    // K4: out = linear_norm(hardswish(o), W_proj) -- tf32 MMA
    gemm_tf32<2><<<dim3(OUT_DIM / 128, (BB * NQ) / 128), 256>>>(
        op, W_proj, gp, bp, mp, vp, (float*)d_out, OUT_DIM);
}

// round 14
// speedup vs baseline: 1.3035x; 1.3035x over previous
#include <cuda_runtime.h>
#include <math.h>
#include <stdint.h>

// ---------------- problem constants ----------------
#define BB   512
#define NN   196          // 14*14
#define NQ   49           // 7*7
#define CC   256
#define HH   8
#define KD   16
#define VD   32
#define KV_DIM 384        // H*(KD+VD)
#define Q_DIM  128        // H*KD
#define V_ATTN 256        // H*VD
#define OUT_DIM 384
#define EPS  1e-5f
#define ATT_SCALE 0.25f   // 16^-0.5

// ---------------- scratch (module-static, allowed) ----------------
__device__ float g_kv_buf[(size_t)BB * NN * KV_DIM];   // 154 MB
__device__ float g_q_buf [(size_t)BB * NQ * Q_DIM];    // 12.8 MB
__device__ float g_o_buf [(size_t)BB * NQ * V_ATTN];   // 25.7 MB
__device__ float g_bias_buf[HH * NQ * NN];             // 307 KB

__device__ __forceinline__ float hswish(float x) {
    float c = fminf(fmaxf(x + 3.0f, 0.0f), 6.0f);
    return x * c * (1.0f / 6.0f);
}

__device__ __forceinline__ uint32_t f2tf(float x) {
    uint32_t r;
    asm("cvt.rna.tf32.f32 %0, %1;" : "=r"(r) : "f"(x));
    return r;
}

__device__ __forceinline__ void mma_tf32(float* c, const uint32_t* a,
                                         uint32_t b0, uint32_t b1) {
    asm volatile(
        "mma.sync.aligned.m16n8k8.row.col.f32.tf32.tf32.f32 "
        "{%0,%1,%2,%3}, {%4,%5,%6,%7}, {%8,%9}, {%0,%1,%2,%3};\n"
        : "+f"(c[0]), "+f"(c[1]), "+f"(c[2]), "+f"(c[3])
        : "r"(a[0]), "r"(a[1]), "r"(a[2]), "r"(a[3]), "r"(b0), "r"(b1));
}

// ---------------------------------------------------------------------------
// TF32 tensor-core GEMM + norm epilogue.
// MODE 0: A' = A;  MODE 1: subsample gather;  MODE 2: hardswish(A).
// ---------------------------------------------------------------------------
template <int MODE>
__global__ __launch_bounds__(256)
void gemm_tf32(const float* __restrict__ A, const float* __restrict__ W,
               const float* __restrict__ gv, const float* __restrict__ bv,
               const float* __restrict__ mv, const float* __restrict__ vv,
               float* __restrict__ out, int Ncols)
{
    __shared__ uint32_t As[2][128][20];
    __shared__ uint32_t Bs[2][128][20];

    const int t    = threadIdx.x;
    const int lane = t & 31;
    const int warp = t >> 5;
    const int wm   = warp >> 1;
    const int wn   = warp & 1;
    const int m0   = blockIdx.y * 128;
    const int n0   = blockIdx.x * 128;

    const int lrow = t >> 2;
    const int lk4  = (t & 3) * 4;

    const float* Aptr[2];
#pragma unroll
    for (int r = 0; r < 2; r++) {
        int gm = m0 + lrow + r * 64;
        if (MODE == 1) {
            int b  = gm / NQ;
            int qq = gm - b * NQ;
            int n  = 28 * (qq / 7) + 2 * (qq % 7);
            Aptr[r] = A + ((size_t)(b * NN + n)) * CC;
        } else {
            Aptr[r] = A + (size_t)gm * CC;
        }
    }
    const float* Bptr[2];
#pragma unroll
    for (int r = 0; r < 2; r++)
        Bptr[r] = W + (size_t)(n0 + lrow + r * 64) * CC;

    float acc[2][8][4];
#pragma unroll
    for (int i = 0; i < 2; i++)
#pragma unroll
        for (int j = 0; j < 8; j++)
#pragma unroll
            for (int k = 0; k < 4; k++) acc[i][j][k] = 0.0f;

    float4 av[2], bv4[2];
#pragma unroll
    for (int r = 0; r < 2; r++) {
        av[r]  = *(const float4*)(Aptr[r] + lk4);
        bv4[r] = *(const float4*)(Bptr[r] + lk4);
    }

    int buf = 0;
    const int lq = lane >> 2;
    const int lr4 = lane & 3;

    for (int c = 0; c < CC / 16; c++) {
#pragma unroll
        for (int r = 0; r < 2; r++) {
            int row = lrow + r * 64;
            float4 a = av[r];
            if (MODE == 2) {
                a.x = hswish(a.x); a.y = hswish(a.y);
                a.z = hswish(a.z); a.w = hswish(a.w);
            }
            As[buf][row][lk4 + 0] = f2tf(a.x);
            As[buf][row][lk4 + 1] = f2tf(a.y);
            As[buf][row][lk4 + 2] = f2tf(a.z);
            As[buf][row][lk4 + 3] = f2tf(a.w);
            Bs[buf][row][lk4 + 0] = f2tf(bv4[r].x);
            Bs[buf][row][lk4 + 1] = f2tf(bv4[r].y);
            Bs[buf][row][lk4 + 2] = f2tf(bv4[r].z);
            Bs[buf][row][lk4 + 3] = f2tf(bv4[r].w);
        }
        __syncthreads();

        if (c + 1 < CC / 16) {
            int k0 = (c + 1) * 16;
#pragma unroll
            for (int r = 0; r < 2; r++) {
                av[r]  = *(const float4*)(Aptr[r] + k0 + lk4);
                bv4[r] = *(const float4*)(Bptr[r] + k0 + lk4);
            }
        }

#pragma unroll
        for (int ks = 0; ks < 16; ks += 8) {
            uint32_t a[2][4];
#pragma unroll
            for (int mt = 0; mt < 2; mt++) {
                int mb = wm * 32 + mt * 16;
                a[mt][0] = As[buf][mb + lq    ][ks + lr4];
                a[mt][1] = As[buf][mb + lq + 8][ks + lr4];
                a[mt][2] = As[buf][mb + lq    ][ks + lr4 + 4];
                a[mt][3] = As[buf][mb + lq + 8][ks + lr4 + 4];
            }
#pragma unroll
            for (int nt = 0; nt < 8; nt++) {
                int nb = wn * 64 + nt * 8;
                uint32_t b0 = Bs[buf][nb + lq][ks + lr4];
                uint32_t b1 = Bs[buf][nb + lq][ks + lr4 + 4];
                mma_tf32(acc[0][nt], a[0], b0, b1);
                mma_tf32(acc[1][nt], a[1], b0, b1);
            }
        }
        buf ^= 1;
    }

#pragma unroll
    for (int mt = 0; mt < 2; mt++) {
        int mrow = m0 + wm * 32 + mt * 16 + lq;
#pragma unroll
        for (int nt = 0; nt < 8; nt++) {
            int n = n0 + wn * 64 + nt * 8 + lr4 * 2;
            float s0 = gv[n]     * rsqrtf(vv[n]     + EPS);
            float s1 = gv[n + 1] * rsqrtf(vv[n + 1] + EPS);
            float m_0 = mv[n], m_1 = mv[n + 1];
            float o_0 = bv[n], o_1 = bv[n + 1];
            const float* cc = acc[mt][nt];
            float2 r0 = { (cc[0] - m_0) * s0 + o_0, (cc[1] - m_1) * s1 + o_1 };
            float2 r1 = { (cc[2] - m_0) * s0 + o_0, (cc[3] - m_1) * s1 + o_1 };
            *(float2*)(out + (size_t)mrow * Ncols + n)       = r0;
            *(float2*)(out + (size_t)(mrow + 8) * Ncols + n) = r1;
        }
    }
}

// ---------------------------------------------------------------------------
// Bias gather precompute: g_bias_buf[h][q][k] = biases[h, bias_idxs[q,k]]
// ---------------------------------------------------------------------------
__global__ void bias_gather(const float* __restrict__ biases,
                            const int* __restrict__ bidx)
{
    const int q = blockIdx.x;
    const int h = blockIdx.y;
    for (int k = threadIdx.x; k < NN; k += blockDim.x)
        g_bias_buf[(h * NQ + q) * NN + k] = biases[h * NN + bidx[q * NN + k]];
}

// ---------------------------------------------------------------------------
// Attention, phase-split 2-pass (static smem <= 48KB):
// Pass A handles queries 0..27 (4/warp), pass B queries 28..48 (3/warp).
// Per pass: load K(pad20)+Q -> QK+softmax (P -> smem) -> overlay V -> AV.
// ---------------------------------------------------------------------------
#define ATT_THREADS 224
#define PASSA_NQ 28
#define BUF_FLOATS (NN * VD)          // 6272 floats, holds K(3920)+Q(784) too

__device__ __forceinline__ void attn_pass(
    int nqw, int passq0, int b, int h, int w, int lane,
    float* __restrict__ ps, float* __restrict__ bufm,
    const float* __restrict__ kvbase, int t)
{
    float* ks0 = bufm;                 // [196][20]
    float* qs  = bufm + NN * 20;       // [nq_pass][16] (indexed by local q)
    const int nq_pass = nqw * 7;

    // ---- load K (padded) and this pass's Q ----
    for (int idx = t; idx < NN * KD; idx += ATT_THREADS) {
        int n = idx >> 4, d = idx & 15;
        ks0[n * 20 + d] = kvbase[n * KV_DIM + d];
    }
    const float* qbase = g_q_buf + (size_t)b * NQ * Q_DIM + h * KD;
    for (int idx = t; idx < nq_pass * KD; idx += ATT_THREADS) {
        int n = idx >> 4, d = idx & 15;
        qs[idx] = qbase[(passq0 + n) * Q_DIM + d];
    }
    __syncthreads();

    // ---- QK + softmax, warp queries sequential ----
    for (int qi = 0; qi < nqw; qi++) {
        const int ql = w * nqw + qi;           // local query in pass
        const int q  = passq0 + ql;            // absolute query
        const float4* qp = (const float4*)(qs + ql * KD);
        float4 q0 = qp[0], q1 = qp[1], q2 = qp[2], q3 = qp[3];
        const float* bgb = g_bias_buf + (h * NQ + q) * NN;

        float lg[7];
#pragma unroll
        for (int s = 0; s < 7; s++) {
            const int k = 32 * s + lane;
            const bool valid = (k < NN);
            const int ksafe = valid ? k : 0;
            const float4* kp = (const float4*)(ks0 + ksafe * 20);
            float4 k0 = kp[0], k1 = kp[1], k2 = kp[2], k3 = kp[3];
            float d0 = q0.x*k0.x + q0.y*k0.y + q0.z*k0.z + q0.w*k0.w
                     + q1.x*k1.x + q1.y*k1.y + q1.z*k1.z + q1.w*k1.w
                     + q2.x*k2.x + q2.y*k2.y + q2.z*k2.z + q2.w*k2.w
                     + q3.x*k3.x + q3.y*k3.y + q3.z*k3.z + q3.w*k3.w;
            lg[s] = -1e30f;
            if (valid) lg[s] = d0 * ATT_SCALE + __ldg(bgb + k);
        }

        float mx = lg[0];
#pragma unroll
        for (int s = 1; s < 7; s++) mx = fmaxf(mx, lg[s]);
#pragma unroll
        for (int o = 16; o > 0; o >>= 1)
            mx = fmaxf(mx, __shfl_xor_sync(0xffffffffu, mx, o));
        float sum = 0.0f;
#pragma unroll
        for (int s = 0; s < 7; s++) {
            float p = __expf(lg[s] - mx);
            lg[s] = p;
            sum += p;
        }
#pragma unroll
        for (int o = 16; o > 0; o >>= 1)
            sum += __shfl_xor_sync(0xffffffffu, sum, o);
        float inv = 1.0f / sum;
#pragma unroll
        for (int s = 0; s < 7; s++) {
            int k = 32 * s + lane;
            if (k < NN) ps[ql * NN + k] = lg[s] * inv;
        }
    }
    __syncthreads();

    // ---- overlay V ----
    for (int idx = t; idx < NN * VD; idx += ATT_THREADS) {
        int n = idx >> 5, d = idx & 31;
        bufm[idx] = kvbase[n * KV_DIM + KD + d];
    }
    __syncthreads();

    // ---- AV: one k-sweep for the warp's nqw queries, lane = vd ----
    float ov[4] = {0.f, 0.f, 0.f, 0.f};
    const float* psw = ps + (w * nqw) * NN;
    for (int kk = 0; kk < NN; kk += 4) {
        float v0 = bufm[(kk + 0) * VD + lane];
        float v1 = bufm[(kk + 1) * VD + lane];
        float v2 = bufm[(kk + 2) * VD + lane];
        float v3 = bufm[(kk + 3) * VD + lane];
        for (int qi = 0; qi < nqw; qi++) {
            float4 p4 = *(const float4*)(psw + qi * NN + kk);  // broadcast
            ov[qi] += p4.x * v0 + p4.y * v1 + p4.z * v2 + p4.w * v3;
        }
    }

    float* obase = g_o_buf +
        ((size_t)(b * NQ + passq0 + w * nqw)) * V_ATTN + h * VD + lane;
    for (int qi = 0; qi < nqw; qi++)
        obase[qi * V_ATTN] = ov[qi];
    __syncthreads();   // before next pass overwrites bufm/ps
}

__global__ __launch_bounds__(ATT_THREADS)
void attn_kernel()
{
    __shared__ float ps[PASSA_NQ * NN];   // 28*196*4 = 21952 B
    __shared__ float bufm[BUF_FLOATS];    // 25088 B  (total 47040 B)

    const int bh = blockIdx.x;
    const int b = bh >> 3, h = bh & 7;
    const int t = threadIdx.x;
    const int w = t >> 5, lane = t & 31;

    const float* kvbase = g_kv_buf + (size_t)b * NN * KV_DIM + h * (KD + VD);

    attn_pass(4, 0,        b, h, w, lane, ps, bufm, kvbase, t);  // q 0..27
    attn_pass(3, PASSA_NQ, b, h, w, lane, ps, bufm, kvbase, t);  // q 28..48
}

// ---------------------------------------------------------------------------
extern "C" void kernel_launch(void* const* d_in, const int* in_sizes, int n_in,
                              void* d_out, int out_size)
{
    const float* x      = (const float*)d_in[0];
    const float* W_kv   = (const float*)d_in[1];
    const float* gkv    = (const float*)d_in[2];
    const float* bkv    = (const float*)d_in[3];
    const float* mkv    = (const float*)d_in[4];
    const float* vkv    = (const float*)d_in[5];
    const float* W_q    = (const float*)d_in[6];
    const float* gq     = (const float*)d_in[7];
    const float* bq     = (const float*)d_in[8];
    const float* mq     = (const float*)d_in[9];
    const float* vq     = (const float*)d_in[10];
    const float* W_proj = (const float*)d_in[11];
    const float* gp     = (const float*)d_in[12];
    const float* bp     = (const float*)d_in[13];
    const float* mp     = (const float*)d_in[14];
    const float* vp     = (const float*)d_in[15];
    const float* biases = (const float*)d_in[16];
    const int*   bidx   = (const int*)  d_in[17];

    float *kvp, *qp, *op;
    cudaGetSymbolAddress((void**)&kvp, g_kv_buf);
    cudaGetSymbolAddress((void**)&qp,  g_q_buf);
    cudaGetSymbolAddress((void**)&op,  g_o_buf);

    // K0: bias gather table (tiny)
    bias_gather<<<dim3(NQ, HH), 196>>>(biases, bidx);

    // K1: kv = linear_norm(x, W_kv)  -- tf32 MMA
    gemm_tf32<0><<<dim3(KV_DIM / 128, (BB * NN) / 128), 256>>>(
        x, W_kv, gkv, bkv, mkv, vkv, kvp, KV_DIM);

    // K2: q = linear_norm(subsample(x), W_q) -- tf32 MMA
    gemm_tf32<1><<<dim3(Q_DIM / 128, (BB * NQ) / 128), 256>>>(
        x, W_q, gq, bq, mq, vq, qp, Q_DIM);

    // K3: attention per (b, h) -- phase-split 2-pass, static smem
    attn_kernel<<<BB * HH, ATT_THREADS>>>();

    // K4: out = linear_norm(hardswish(o), W_proj) -- tf32 MMA
    gemm_tf32<2><<<dim3(OUT_DIM / 128, (BB * NQ) / 128), 256>>>(
        op, W_proj, gp, bp, mp, vp, (float*)d_out, OUT_DIM);
}